// round 12
// baseline (speedup 1.0000x reference)
#include <cuda_runtime.h>
#include <math.h>

#define Lq 256
#define Dm 300
#define Sm 16
#define SK 16
#define Em 2048
#define Cm 7
#define NEGV -1000000000.0f

// ---------------- scratch (device globals; no allocation) ----------------
__device__ float g_Lin[Lq * 1800];       // [P0 | P1 | Hself | Q | K | V] per row
__device__ float g_hidden[Lq * Dm];
__device__ float g_ctx[Lq * Dm];
__device__ float g_relatt[Lq * Dm];
__device__ float g_nodes[Lq * 48 * Dm];  // 14.7 MB
__device__ float g_score[Lq * 48];
__device__ int   g_nmask[Lq * 48];
__device__ float g_sym[Lq * Dm];
__device__ float g_part[2 * Lq * 1800];  // split-K partials (max: Lin KS=2), 3.7 MB

struct BPtrs { const float* p[6]; };

__device__ __forceinline__ float warp_sum(float v) {
#pragma unroll
    for (int o = 16; o; o >>= 1) v += __shfl_xor_sync(0xffffffffu, v, o);
    return v;
}
__device__ __forceinline__ float warp_max(float v) {
#pragma unroll
    for (int o = 16; o; o >>= 1) v = fmaxf(v, __shfl_xor_sync(0xffffffffu, v, o));
    return v;
}

// ---------------- split-K tiled SGEMM ----------------
// AMODE 0: A is the passed pointer, row-major M x Kd
// AMODE 1: A row l is the concat [g_hidden[l] | g_relatt[l] | g_sym[l]] (Kd = 900)
// BMODE 0: B = B.p[0], row-major Kd x N (ldb = N)
// BMODE 1: six concatenated 300x300 matrices: N = 1800, col c -> matrix c/300
// blockIdx.z = split-K slice; writes partial sums to Cpart[z * M*N + ...]
template <int AMODE, int BMODE>
__global__ __launch_bounds__(256)
void sgemm_splitk(const float* __restrict__ A, BPtrs B, float* __restrict__ Cpart,
                  int M, int N, int Kd, int kChunk)
{
    const int BM = 64, BN = 64, BK = 16;
    __shared__ float As[BK][BM];
    __shared__ float Bs[BK][BN];
    int tid = threadIdx.x;                 // 256 threads
    int tx = tid & 15, ty = tid >> 4;
    int rowBase = blockIdx.y * BM;
    int colBase = blockIdx.x * BN;
    int ks = blockIdx.z;
    int kBeg = ks * kChunk;
    int kEnd = min(Kd, kBeg + kChunk);
    float acc[4][4];
#pragma unroll
    for (int i = 0; i < 4; i++)
#pragma unroll
        for (int j = 0; j < 4; j++) acc[i][j] = 0.f;

    for (int k0 = kBeg; k0 < kEnd; k0 += BK) {
#pragma unroll
        for (int i = tid; i < BM * BK; i += 256) {
            int r = i >> 4, kk = i & 15;
            int gr = rowBase + r, gk = k0 + kk;
            float v = 0.f;
            if (gr < M && gk < kEnd) {
                if (AMODE == 1) {
                    if (gk < 300)      v = g_hidden[gr * 300 + gk];
                    else if (gk < 600) v = g_relatt[gr * 300 + gk - 300];
                    else               v = g_sym[gr * 300 + gk - 600];
                } else {
                    v = A[gr * Kd + gk];
                }
            }
            As[kk][r] = v;
        }
#pragma unroll
        for (int i = tid; i < BK * BN; i += 256) {
            int kk = i >> 6, c = i & 63;
            int gk = k0 + kk, gc = colBase + c;
            float v = 0.f;
            if (gk < kEnd && gc < N) {
                if (BMODE == 1) { int m = gc / 300; int o = gc - m * 300; v = B.p[m][gk * 300 + o]; }
                else            { v = B.p[0][gk * N + gc]; }
            }
            Bs[kk][c] = v;
        }
        __syncthreads();
#pragma unroll
        for (int kk = 0; kk < BK; kk++) {
            float ra[4], rb[4];
#pragma unroll
            for (int i = 0; i < 4; i++) ra[i] = As[kk][ty * 4 + i];
#pragma unroll
            for (int j = 0; j < 4; j++) rb[j] = Bs[kk][tx * 4 + j];
#pragma unroll
            for (int i = 0; i < 4; i++)
#pragma unroll
                for (int j = 0; j < 4; j++) acc[i][j] += ra[i] * rb[j];
        }
        __syncthreads();
    }
    float* Cp = Cpart + (size_t)ks * M * N;
#pragma unroll
    for (int i = 0; i < 4; i++) {
        int gr = rowBase + ty * 4 + i;
        if (gr >= M) continue;
#pragma unroll
        for (int j = 0; j < 4; j++) {
            int gc = colBase + tx * 4 + j;
            if (gc >= N) continue;
            Cp[gr * N + gc] = acc[i][j];
        }
    }
}

// ---------------- split-K reduction: out[i] = sum_ks part[ks][i] ----------------
__global__ __launch_bounds__(256)
void reduce_splitk(const float4* __restrict__ part, float4* __restrict__ out,
                   int n4, int KS)
{
    int i = blockIdx.x * blockDim.x + threadIdx.x;
    if (i >= n4) return;
    float4 a = part[i];
    for (int ks = 1; ks < KS; ks++) {
        float4 b = part[(size_t)ks * n4 + i];
        a.x += b.x; a.y += b.y; a.z += b.z; a.w += b.w;
    }
    out[i] = a;
}

// ---------------- merged RGCN + windowed attention (both read only g_Lin) ----------------
// blocks [0, Lq):   RGCN for l = blockIdx.x
// blocks [Lq, 2Lq): windowed attention for l = blockIdx.x - Lq
__global__ __launch_bounds__(256)
void k_rgcn_relatt(const float* __restrict__ b_rgcn,
                   const int* __restrict__ esrc, const int* __restrict__ edst,
                   const int* __restrict__ etyp, const float* __restrict__ comp)
{
    int tid = threadIdx.x;  // 256
    if (blockIdx.x < Lq) {
        // ---- RGCN ----
        int l = blockIdx.x;
        __shared__ int sdst[Em];
        for (int i = tid; i < Em; i += 256) sdst[i] = edst[i];
        int d0 = tid, d1 = tid + 256;
        bool h1 = (d1 < Dm);
        float acc0 = g_Lin[l * 1800 + 600 + d0] + b_rgcn[d0];
        float acc1 = h1 ? g_Lin[l * 1800 + 600 + d1] + b_rgcn[d1] : 0.f;
        __syncthreads();
        for (int e = 0; e < Em; e++) {
            if (sdst[e] == l) {
                int s = esrc[e]; int t = etyp[e];
                float c0 = comp[2 * t], c1 = comp[2 * t + 1];
                const float* p0 = g_Lin + s * 1800;
                const float* p1 = p0 + 300;
                acc0 += c0 * p0[d0] + c1 * p1[d0];
                if (h1) acc1 += c0 * p0[d1] + c1 * p1[d1];
            }
        }
        g_hidden[l * Dm + d0] = acc0;
        if (h1) g_hidden[l * Dm + d1] = acc1;
    } else {
        // ---- windowed attention (middle query only) -> ctx ----
        int l = blockIdx.x - Lq;
        int w = tid >> 5, lane = tid & 31;
        __shared__ float ssc[2][3];
        __shared__ float sat[2][3];
        int w0 = max(l - 1, 0), w1 = l, w2 = min(l + 1, Lq - 1);
        int wins[3] = {w0, w1, w2};
        if (w < 6) {
            int h = w / 3, j = w - h * 3;
            const float* q  = g_Lin + l * 1800 + 900 + h * 150;
            const float* kk = g_Lin + wins[j] * 1800 + 1200 + h * 150;
            float a = 0.f;
            for (int d = lane; d < 150; d += 32) a += q[d] * kk[d];
            a = warp_sum(a);
            if (lane == 0) ssc[h][j] = a * (1.0f / sqrtf(150.0f));
        }
        __syncthreads();
        if (tid < 2) {
            int h = tid;
            float m = fmaxf(ssc[h][0], fmaxf(ssc[h][1], ssc[h][2]));
            float e0 = __expf(ssc[h][0] - m), e1 = __expf(ssc[h][1] - m), e2 = __expf(ssc[h][2] - m);
            float inv = 1.0f / (e0 + e1 + e2);
            sat[h][0] = e0 * inv; sat[h][1] = e1 * inv; sat[h][2] = e2 * inv;
        }
        __syncthreads();
        for (int d = tid; d < Dm; d += 256) {
            int h = d / 150;
            float v = sat[h][0] * g_Lin[w0 * 1800 + 1500 + d]
                    + sat[h][1] * g_Lin[w1 * 1800 + 1500 + d]
                    + sat[h][2] * g_Lin[w2 * 1800 + 1500 + d];
            g_ctx[l * Dm + d] = v;
        }
    }
}

// ---------------- concept-graph node builder: one block per (b,l,s), 256 threads ----------------
__global__ __launch_bounds__(256)
void k_nodes(const float* __restrict__ table,
             const int* __restrict__ src_ids, const int* __restrict__ dst_ids,
             const float* __restrict__ wgt, const float* __restrict__ sentic,
             const float* __restrict__ rvecs)
{
    int idx = blockIdx.x;
    int s = idx & 15;
    int l = (idx >> 4) & 255;
    int b = idx >> 12;
    int n = b * Sm + s;
    int tid = threadIdx.x;            // 256
    int w = tid >> 5, lane = tid & 31;

    __shared__ float sm_rel[Dm], sm_src[Dm], sm_rv[Dm], sm_sr[Dm];
    __shared__ float sm_dst[SK][Dm];
    __shared__ float sm_d1[SK], sm_nr[SK], sm_d2[SK], sm_coef[SK];
    __shared__ int sm_id[SK];
    __shared__ float sm_red[8];
    __shared__ float sm_rn;

    int sid = src_ids[(b * Lq + l) * Sm + s];
    int nrow = (l * 48 + n) * Dm;
    if (sid < 0) {
        // no zero-fill of g_nodes needed: k_sym weights these rows with att==0 exactly
        if (tid == 0) { g_score[l * 48 + n] = NEGV; g_nmask[l * 48 + n] = 0; }
        return;
    }
    if (tid < SK) sm_id[tid] = dst_ids[((b * Lq + l) * Sm + s) * SK + tid];

    float pn = 0.f;
    // rows are 300 floats = 1200 B -> 16B-aligned float4 loads (75 per row)
    {
        const float4* relr = (const float4*)(g_relatt + l * Dm);
        const float4* srcr = (const float4*)(table + (long)sid * Dm);
        const float4* rvr  = (const float4*)(rvecs + b * Dm);
        for (int i = tid; i < 75; i += 256) {
            float4 rr = relr[i];
            float4 sv = srcr[i];
            float4 rv = rvr[i];
            ((float4*)sm_rel)[i] = rr;
            ((float4*)sm_src)[i] = sv;
            ((float4*)sm_rv)[i]  = rv;
            float4 sr; sr.x = sv.x * rv.x; sr.y = sv.y * rv.y; sr.z = sv.z * rv.z; sr.w = sv.w * rv.w;
            ((float4*)sm_sr)[i] = sr;
            pn += rr.x * rr.x + rr.y * rr.y + rr.z * rr.z + rr.w * rr.w;
        }
    }
    pn = warp_sum(pn);
    if (lane == 0) sm_red[w] = pn;
    __syncthreads();
    if (tid == 0) {
        float t = 0.f;
#pragma unroll
        for (int i = 0; i < 8; i++) t += sm_red[i];
        sm_rn = sqrtf(t);
    }
    __syncthreads();

    // gather 16 dst rows, float4-flattened: 16 * 75 = 1200 float4 elements, 256 threads
    for (int i = tid; i < SK * 75; i += 256) {
        int k = i / 75, d4 = i - k * 75;
        int id = sm_id[k];
        float4 v;
        if (id >= 0) v = ((const float4*)(table + (long)id * Dm))[d4];
        else         { v.x = v.y = v.z = v.w = 0.f; }
        ((float4*)(&sm_dst[k][0]))[d4] = v;
    }
    __syncthreads();

    // 8 warps x 2 k's each: three dots per k
    for (int k = w; k < SK; k += 8) {
        float a1 = 0.f, a2 = 0.f, a3 = 0.f;
        for (int d = lane; d < Dm; d += 32) {
            float x = sm_dst[k][d];
            a1 += sm_rel[d] * x;
            a2 += x * x;
            a3 += sm_sr[d] * x;
        }
        a1 = warp_sum(a1); a2 = warp_sum(a2); a3 = warp_sum(a3);
        if (lane == 0) { sm_d1[k] = a1; sm_nr[k] = a2; sm_d2[k] = a3; }
    }
    __syncthreads();

    if (tid < 32) {
        int k = lane;
        bool valid = (k < SK) && (sm_id[k] >= 0);
        float omega = -INFINITY;
        if (valid) {
            long base = ((long)(b * Lq + l) * Sm + s) * SK + k;
            float cosv = fabsf(sm_d1[k]) / (sm_rn * sqrtf(sm_nr[k]) + 1e-8f);
            omega = 0.5f * wgt[base] * cosv + 0.5f * fabsf(sentic[base]);
        }
        float m = warp_max(omega);
        float e = valid ? __expf(omega - m) : 0.f;
        float ssum = warp_sum(e);
        float alpha1 = (ssum > 0.f) ? e / ssum : 0.f;
        float sv = valid ? alpha1 * sm_d2[k] : -INFINITY;
        float m2 = warp_max(sv);
        float e2 = valid ? __expf(sv - m2) : 0.f;
        float ssum2 = warp_sum(e2);
        float alpha2 = (ssum2 > 0.f) ? e2 / ssum2 : 0.f;
        if (k < SK) sm_coef[k] = alpha1 * alpha2;
    }
    __syncthreads();

    float psc = 0.f;
    for (int d = tid; d < Dm; d += 256) {
        float a = 0.f;
#pragma unroll
        for (int k = 0; k < SK; k++) a += sm_coef[k] * sm_dst[k][d];
        float nd = sm_src[d] + sm_rv[d] * a;
        g_nodes[nrow + d] = nd;
        psc += nd * sm_rel[d];
    }
    psc = warp_sum(psc);
    if (lane == 0) sm_red[w] = psc;
    __syncthreads();
    if (tid == 0) {
        float t = 0.f;
#pragma unroll
        for (int i = 0; i < 8; i++) t += sm_red[i];
        g_score[l * 48 + n] = t;
        g_nmask[l * 48 + n] = 1;
    }
}

// ---------------- node-level attention -> sym ----------------
__global__ __launch_bounds__(256)
void k_sym()
{
    int l = blockIdx.x;
    int tid = threadIdx.x;  // 256
    __shared__ float att[48];
    __shared__ int sany;
    if (tid == 0) {
        float m = -INFINITY; int any = 0;
        for (int nn = 0; nn < 48; nn++)
            if (g_nmask[l * 48 + nn]) { any = 1; m = fmaxf(m, g_score[l * 48 + nn]); }
        float ssum = 0.f;
        for (int nn = 0; nn < 48; nn++) {
            float e = g_nmask[l * 48 + nn] ? __expf(g_score[l * 48 + nn] - m) : 0.f;
            att[nn] = e; ssum += e;
        }
        float inv = (ssum > 0.f) ? 1.f / ssum : 0.f;
        for (int nn = 0; nn < 48; nn++) att[nn] *= inv;
        sany = any;
    }
    __syncthreads();
    for (int d = tid; d < Dm; d += 256) {
        float a = 0.f;
#pragma unroll 8
        for (int nn = 0; nn < 48; nn++) {
            float c = att[nn];
            if (c != 0.f) a += c * g_nodes[(l * 48 + nn) * Dm + d];
        }
        g_sym[l * Dm + d] = sany ? a : 0.f;
    }
}

// ---------------- fused: split-K reduce (fuse GEMM, +bias+relu) + head + log_softmax ----------------
// one block per row l; reads g_part slices, keeps the fused row in smem, writes final output
__global__ __launch_bounds__(256)
void k_reduce_out(const float* __restrict__ part, const float* __restrict__ bfuse,
                  const float* __restrict__ Wout, const float* __restrict__ bout,
                  float* __restrict__ out)
{
    int l = blockIdx.x;
    int tid = threadIdx.x;  // 256
    int w = tid >> 5, lane = tid & 31;
    __shared__ float hs[Dm];
    __shared__ float logits[8];
    __shared__ float lse;
    for (int d = tid; d < Dm; d += 256) {
        float a = 0.f;
#pragma unroll
        for (int ks = 0; ks < 6; ks++) a += part[(size_t)ks * (Lq * Dm) + l * Dm + d];
        a += bfuse[d];
        hs[d] = fmaxf(a, 0.f);
    }
    __syncthreads();
    if (w < Cm) {
        float a = 0.f;
        for (int d = lane; d < Dm; d += 32) a += hs[d] * Wout[d * Cm + w];
        a = warp_sum(a);
        if (lane == 0) logits[w] = a + bout[w];
    }
    __syncthreads();
    if (tid == 0) {
        float m = logits[0];
        for (int c = 1; c < Cm; c++) m = fmaxf(m, logits[c]);
        float ssum = 0.f;
        for (int c = 0; c < Cm; c++) ssum += __expf(logits[c] - m);
        lse = m + logf(ssum);
    }
    __syncthreads();
    if (tid < Cm) out[l * Cm + tid] = logits[tid] - lse;
}

// ---------------- launch ----------------
extern "C" void kernel_launch(void* const* d_in, const int* in_sizes, int n_in,
                              void* d_out, int out_size)
{
    (void)in_sizes; (void)n_in; (void)out_size;
    const float* utt   = (const float*)d_in[0];
    const int*   esrc  = (const int*)d_in[1];
    const int*   edst  = (const int*)d_in[2];
    const int*   etyp  = (const int*)d_in[3];
    const int*   csrc  = (const int*)d_in[4];
    const int*   cdst  = (const int*)d_in[5];
    const float* cwgt  = (const float*)d_in[6];
    const float* csen  = (const float*)d_in[7];
    const float* table = (const float*)d_in[8];
    const float* Wb    = (const float*)d_in[9];
    const float* comp  = (const float*)d_in[10];
    const float* Wself = (const float*)d_in[11];
    const float* brg   = (const float*)d_in[12];
    const float* Wq    = (const float*)d_in[13];
    const float* Wk    = (const float*)d_in[14];
    const float* Wv    = (const float*)d_in[15];
    const float* Wo    = (const float*)d_in[16];
    const float* rvec  = (const float*)d_in[17];
    const float* Wfuse = (const float*)d_in[18];
    const float* bfuse = (const float*)d_in[19];
    const float* Wout  = (const float*)d_in[20];
    const float* bout  = (const float*)d_in[21];

    // host-side symbol lookups (no stream ops, capture-safe); cached across calls
    static float* pLin = nullptr; static float* pCtx = nullptr; static float* pRel = nullptr;
    static float* pPart = nullptr;
    if (!pLin) {
        cudaGetSymbolAddress((void**)&pLin,  g_Lin);
        cudaGetSymbolAddress((void**)&pCtx,  g_ctx);
        cudaGetSymbolAddress((void**)&pRel,  g_relatt);
        cudaGetSymbolAddress((void**)&pPart, g_part);
    }

    // 1) six fused linears: [P0|P1|Hself|Q|K|V] = utt @ [Wb0|Wb1|Wself|Wq|Wk|Wv]
    //    split-K=2 (kChunk 160): grid 29x4x2 = 232 blocks
    BPtrs six; six.p[0] = Wb; six.p[1] = Wb + 300 * 300; six.p[2] = Wself;
    six.p[3] = Wq; six.p[4] = Wk; six.p[5] = Wv;
    sgemm_splitk<0, 1><<<dim3(29, 4, 2), 256>>>(utt, six, pPart, Lq, 1800, Dm, 160);
    reduce_splitk<<<(Lq * 1800 / 4 + 255) / 256, 256>>>((const float4*)pPart, (float4*)pLin,
                                                        Lq * 1800 / 4, 2);

    // 2) merged RGCN + windowed attention (512 blocks; both read only g_Lin)
    k_rgcn_relatt<<<2 * Lq, 256>>>(brg, esrc, edst, etyp, comp);

    // 3) ctx @ Wo with split-K=4 (80/80/80/60): 80 blocks
    BPtrs bo; bo.p[0] = Wo; bo.p[1] = bo.p[2] = bo.p[3] = bo.p[4] = bo.p[5] = nullptr;
    sgemm_splitk<0, 0><<<dim3(5, 4, 4), 256>>>(pCtx, bo, pPart, Lq, Dm, Dm, 80);
    reduce_splitk<<<(Lq * Dm / 4 + 255) / 256, 256>>>((const float4*)pPart, (float4*)pRel,
                                                      Lq * Dm / 4, 4);

    // 4) concept-graph nodes (gather-heavy; 256 threads for 2x gather MLP)
    k_nodes<<<3 * Lq * Sm, 256>>>(table, csrc, cdst, cwgt, csen, rvec);

    // 5) node attention -> sym
    k_sym<<<Lq, 256>>>();

    // 6) fused [hidden|relatt|sym] @ Wfuse, split-K=6 (kChunk 160): 120 blocks
    BPtrs bf; bf.p[0] = Wfuse; bf.p[1] = bf.p[2] = bf.p[3] = bf.p[4] = bf.p[5] = nullptr;
    sgemm_splitk<1, 0><<<dim3(5, 4, 6), 256>>>(nullptr, bf, pPart, Lq, Dm, 900, 160);

    // 7) fused: reduce(+bias+relu) + head + log_softmax, one block per row
    k_reduce_out<<<Lq, 256>>>(pPart, bfuse, Wout, bout, (float*)d_out);
}

// round 13
// speedup vs baseline: 1.0226x; 1.0226x over previous
#include <cuda_runtime.h>
#include <math.h>

#define Lq 256
#define Dm 300
#define Sm 16
#define SK 16
#define Em 2048
#define Cm 7
#define NEGV -1000000000.0f

// ---------------- scratch (device globals; no allocation) ----------------
__device__ float g_Lin[Lq * 1800];       // [P0 | P1 | Hself | Q | K | V] per row
__device__ float g_hidden[Lq * Dm];
__device__ float g_ctx[Lq * Dm];
__device__ float g_relatt[Lq * Dm];
__device__ float g_nodes[Lq * 48 * Dm];  // 14.7 MB
__device__ float g_score[Lq * 48];
__device__ int   g_nmask[Lq * 48];
__device__ float g_sym[Lq * Dm];
__device__ float g_part[4 * Lq * 1800];  // split-K partials (max: Lin KS=4), 7.4 MB

struct BPtrs { const float* p[6]; };

__device__ __forceinline__ float warp_sum(float v) {
#pragma unroll
    for (int o = 16; o; o >>= 1) v += __shfl_xor_sync(0xffffffffu, v, o);
    return v;
}
__device__ __forceinline__ float warp_max(float v) {
#pragma unroll
    for (int o = 16; o; o >>= 1) v = fmaxf(v, __shfl_xor_sync(0xffffffffu, v, o));
    return v;
}

// ---------------- split-K tiled SGEMM ----------------
// AMODE 0: A is the passed pointer, row-major M x Kd
// AMODE 1: A row l is the concat [g_hidden[l] | g_relatt[l] | g_sym[l]] (Kd = 900)
// BMODE 0: B = B.p[0], row-major Kd x N (ldb = N)
// BMODE 1: six concatenated 300x300 matrices: N = 1800, col c -> matrix c/300
// blockIdx.z = split-K slice; writes partial sums to Cpart[z * M*N + ...]
template <int AMODE, int BMODE>
__global__ __launch_bounds__(256)
void sgemm_splitk(const float* __restrict__ A, BPtrs B, float* __restrict__ Cpart,
                  int M, int N, int Kd, int kChunk)
{
    const int BM = 64, BN = 64, BK = 16;
    __shared__ float As[BK][BM];
    __shared__ float Bs[BK][BN];
    int tid = threadIdx.x;                 // 256 threads
    int tx = tid & 15, ty = tid >> 4;
    int rowBase = blockIdx.y * BM;
    int colBase = blockIdx.x * BN;
    int ks = blockIdx.z;
    int kBeg = ks * kChunk;
    int kEnd = min(Kd, kBeg + kChunk);
    float acc[4][4];
#pragma unroll
    for (int i = 0; i < 4; i++)
#pragma unroll
        for (int j = 0; j < 4; j++) acc[i][j] = 0.f;

    for (int k0 = kBeg; k0 < kEnd; k0 += BK) {
#pragma unroll
        for (int i = tid; i < BM * BK; i += 256) {
            int r = i >> 4, kk = i & 15;
            int gr = rowBase + r, gk = k0 + kk;
            float v = 0.f;
            if (gr < M && gk < kEnd) {
                if (AMODE == 1) {
                    if (gk < 300)      v = g_hidden[gr * 300 + gk];
                    else if (gk < 600) v = g_relatt[gr * 300 + gk - 300];
                    else               v = g_sym[gr * 300 + gk - 600];
                } else {
                    v = A[gr * Kd + gk];
                }
            }
            As[kk][r] = v;
        }
#pragma unroll
        for (int i = tid; i < BK * BN; i += 256) {
            int kk = i >> 6, c = i & 63;
            int gk = k0 + kk, gc = colBase + c;
            float v = 0.f;
            if (gk < kEnd && gc < N) {
                if (BMODE == 1) { int m = gc / 300; int o = gc - m * 300; v = B.p[m][gk * 300 + o]; }
                else            { v = B.p[0][gk * N + gc]; }
            }
            Bs[kk][c] = v;
        }
        __syncthreads();
#pragma unroll
        for (int kk = 0; kk < BK; kk++) {
            float ra[4], rb[4];
#pragma unroll
            for (int i = 0; i < 4; i++) ra[i] = As[kk][ty * 4 + i];
#pragma unroll
            for (int j = 0; j < 4; j++) rb[j] = Bs[kk][tx * 4 + j];
#pragma unroll
            for (int i = 0; i < 4; i++)
#pragma unroll
                for (int j = 0; j < 4; j++) acc[i][j] += ra[i] * rb[j];
        }
        __syncthreads();
    }
    float* Cp = Cpart + (size_t)ks * M * N;
#pragma unroll
    for (int i = 0; i < 4; i++) {
        int gr = rowBase + ty * 4 + i;
        if (gr >= M) continue;
#pragma unroll
        for (int j = 0; j < 4; j++) {
            int gc = colBase + tx * 4 + j;
            if (gc >= N) continue;
            Cp[gr * N + gc] = acc[i][j];
        }
    }
}

// ---------------- split-K reduction: out[i] = sum_ks part[ks][i] ----------------
__global__ __launch_bounds__(256)
void reduce_splitk(const float4* __restrict__ part, float4* __restrict__ out,
                   int n4, int KS)
{
    int i = blockIdx.x * blockDim.x + threadIdx.x;
    if (i >= n4) return;
    float4 a = part[i];
    for (int ks = 1; ks < KS; ks++) {
        float4 b = part[(size_t)ks * n4 + i];
        a.x += b.x; a.y += b.y; a.z += b.z; a.w += b.w;
    }
    out[i] = a;
}

// ---------------- merged RGCN + windowed attention (both read only g_Lin) ----------------
__global__ __launch_bounds__(256)
void k_rgcn_relatt(const float* __restrict__ b_rgcn,
                   const int* __restrict__ esrc, const int* __restrict__ edst,
                   const int* __restrict__ etyp, const float* __restrict__ comp)
{
    int tid = threadIdx.x;  // 256
    if (blockIdx.x < Lq) {
        // ---- RGCN ----
        int l = blockIdx.x;
        __shared__ int sdst[Em];
        for (int i = tid; i < Em; i += 256) sdst[i] = edst[i];
        int d0 = tid, d1 = tid + 256;
        bool h1 = (d1 < Dm);
        float acc0 = g_Lin[l * 1800 + 600 + d0] + b_rgcn[d0];
        float acc1 = h1 ? g_Lin[l * 1800 + 600 + d1] + b_rgcn[d1] : 0.f;
        __syncthreads();
        for (int e = 0; e < Em; e++) {
            if (sdst[e] == l) {
                int s = esrc[e]; int t = etyp[e];
                float c0 = comp[2 * t], c1 = comp[2 * t + 1];
                const float* p0 = g_Lin + s * 1800;
                const float* p1 = p0 + 300;
                acc0 += c0 * p0[d0] + c1 * p1[d0];
                if (h1) acc1 += c0 * p0[d1] + c1 * p1[d1];
            }
        }
        g_hidden[l * Dm + d0] = acc0;
        if (h1) g_hidden[l * Dm + d1] = acc1;
    } else {
        // ---- windowed attention (middle query only) -> ctx ----
        int l = blockIdx.x - Lq;
        int w = tid >> 5, lane = tid & 31;
        __shared__ float ssc[2][3];
        __shared__ float sat[2][3];
        int w0 = max(l - 1, 0), w1 = l, w2 = min(l + 1, Lq - 1);
        int wins[3] = {w0, w1, w2};
        if (w < 6) {
            int h = w / 3, j = w - h * 3;
            const float* q  = g_Lin + l * 1800 + 900 + h * 150;
            const float* kk = g_Lin + wins[j] * 1800 + 1200 + h * 150;
            float a = 0.f;
            for (int d = lane; d < 150; d += 32) a += q[d] * kk[d];
            a = warp_sum(a);
            if (lane == 0) ssc[h][j] = a * (1.0f / sqrtf(150.0f));
        }
        __syncthreads();
        if (tid < 2) {
            int h = tid;
            float m = fmaxf(ssc[h][0], fmaxf(ssc[h][1], ssc[h][2]));
            float e0 = __expf(ssc[h][0] - m), e1 = __expf(ssc[h][1] - m), e2 = __expf(ssc[h][2] - m);
            float inv = 1.0f / (e0 + e1 + e2);
            sat[h][0] = e0 * inv; sat[h][1] = e1 * inv; sat[h][2] = e2 * inv;
        }
        __syncthreads();
        for (int d = tid; d < Dm; d += 256) {
            int h = d / 150;
            float v = sat[h][0] * g_Lin[w0 * 1800 + 1500 + d]
                    + sat[h][1] * g_Lin[w1 * 1800 + 1500 + d]
                    + sat[h][2] * g_Lin[w2 * 1800 + 1500 + d];
            g_ctx[l * Dm + d] = v;
        }
    }
}

// ---------------- concept-graph node builder: one block per (b,l,s), 256 threads ----------------
// single merged gather wave: dst rows + rel + src + rv issued together
__global__ __launch_bounds__(256)
void k_nodes(const float* __restrict__ table,
             const int* __restrict__ src_ids, const int* __restrict__ dst_ids,
             const float* __restrict__ wgt, const float* __restrict__ sentic,
             const float* __restrict__ rvecs)
{
    int idx = blockIdx.x;
    int s = idx & 15;
    int l = (idx >> 4) & 255;
    int b = idx >> 12;
    int n = b * Sm + s;
    int tid = threadIdx.x;            // 256
    int w = tid >> 5, lane = tid & 31;

    __shared__ float sm_rel[Dm], sm_src[Dm], sm_rv[Dm], sm_sr[Dm];
    __shared__ float sm_dst[SK][Dm];
    __shared__ float sm_d1[SK], sm_nr[SK], sm_d2[SK], sm_coef[SK];
    __shared__ int sm_id[SK];
    __shared__ float sm_red[8];
    __shared__ float sm_rn;

    int sid = src_ids[(b * Lq + l) * Sm + s];
    int nrow = (l * 48 + n) * Dm;
    if (sid < 0) {
        // no zero-fill of g_nodes needed: k_sym weights these rows with att==0 exactly
        if (tid == 0) { g_score[l * 48 + n] = NEGV; g_nmask[l * 48 + n] = 0; }
        return;
    }
    if (tid < SK) sm_id[tid] = dst_ids[((b * Lq + l) * Sm + s) * SK + tid];
    __syncthreads();

    // ---- single gather wave: 1200 dst f4 + 75 rel + 75 src + 75 rv = 1425 float4 loads
    {
        const float4* relr = (const float4*)(g_relatt + l * Dm);
        const float4* srcr = (const float4*)(table + (long)sid * Dm);
        const float4* rvr  = (const float4*)(rvecs + b * Dm);
        for (int i = tid; i < 1425; i += 256) {
            if (i < 1200) {
                int k = i / 75, d4 = i - k * 75;
                int id = sm_id[k];
                float4 v;
                if (id >= 0) v = ((const float4*)(table + (long)id * Dm))[d4];
                else         { v.x = v.y = v.z = v.w = 0.f; }
                ((float4*)(&sm_dst[k][0]))[d4] = v;
            } else if (i < 1275) {
                ((float4*)sm_rel)[i - 1200] = relr[i - 1200];
            } else if (i < 1350) {
                ((float4*)sm_src)[i - 1275] = srcr[i - 1275];
            } else {
                ((float4*)sm_rv)[i - 1350] = rvr[i - 1350];
            }
        }
    }
    __syncthreads();

    // pn = |rel|^2 ; sm_sr = src * rv
    float pn = 0.f;
    for (int d = tid; d < Dm; d += 256) {
        float r = sm_rel[d];
        pn += r * r;
        sm_sr[d] = sm_src[d] * sm_rv[d];
    }
    pn = warp_sum(pn);
    if (lane == 0) sm_red[w] = pn;
    __syncthreads();
    if (tid == 0) {
        float t = 0.f;
#pragma unroll
        for (int i = 0; i < 8; i++) t += sm_red[i];
        sm_rn = sqrtf(t);
    }
    __syncthreads();

    // 8 warps x 2 k's each: three dots per k
    for (int k = w; k < SK; k += 8) {
        float a1 = 0.f, a2 = 0.f, a3 = 0.f;
        for (int d = lane; d < Dm; d += 32) {
            float x = sm_dst[k][d];
            a1 += sm_rel[d] * x;
            a2 += x * x;
            a3 += sm_sr[d] * x;
        }
        a1 = warp_sum(a1); a2 = warp_sum(a2); a3 = warp_sum(a3);
        if (lane == 0) { sm_d1[k] = a1; sm_nr[k] = a2; sm_d2[k] = a3; }
    }
    __syncthreads();

    if (tid < 32) {
        int k = lane;
        bool valid = (k < SK) && (sm_id[k] >= 0);
        float omega = -INFINITY;
        if (valid) {
            long base = ((long)(b * Lq + l) * Sm + s) * SK + k;
            float cosv = fabsf(sm_d1[k]) / (sm_rn * sqrtf(sm_nr[k]) + 1e-8f);
            omega = 0.5f * wgt[base] * cosv + 0.5f * fabsf(sentic[base]);
        }
        float m = warp_max(omega);
        float e = valid ? __expf(omega - m) : 0.f;
        float ssum = warp_sum(e);
        float alpha1 = (ssum > 0.f) ? e / ssum : 0.f;
        float sv = valid ? alpha1 * sm_d2[k] : -INFINITY;
        float m2 = warp_max(sv);
        float e2 = valid ? __expf(sv - m2) : 0.f;
        float ssum2 = warp_sum(e2);
        float alpha2 = (ssum2 > 0.f) ? e2 / ssum2 : 0.f;
        if (k < SK) sm_coef[k] = alpha1 * alpha2;
    }
    __syncthreads();

    float psc = 0.f;
    for (int d = tid; d < Dm; d += 256) {
        float a = 0.f;
#pragma unroll
        for (int k = 0; k < SK; k++) a += sm_coef[k] * sm_dst[k][d];
        float nd = sm_src[d] + sm_rv[d] * a;
        g_nodes[nrow + d] = nd;
        psc += nd * sm_rel[d];
    }
    psc = warp_sum(psc);
    if (lane == 0) sm_red[w] = psc;
    __syncthreads();
    if (tid == 0) {
        float t = 0.f;
#pragma unroll
        for (int i = 0; i < 8; i++) t += sm_red[i];
        g_score[l * 48 + n] = t;
        g_nmask[l * 48 + n] = 1;
    }
}

// ---------------- node-level attention -> sym ----------------
__global__ __launch_bounds__(256)
void k_sym()
{
    int l = blockIdx.x;
    int tid = threadIdx.x;  // 256
    __shared__ float att[48];
    __shared__ int sany;
    if (tid == 0) {
        float m = -INFINITY; int any = 0;
        for (int nn = 0; nn < 48; nn++)
            if (g_nmask[l * 48 + nn]) { any = 1; m = fmaxf(m, g_score[l * 48 + nn]); }
        float ssum = 0.f;
        for (int nn = 0; nn < 48; nn++) {
            float e = g_nmask[l * 48 + nn] ? __expf(g_score[l * 48 + nn] - m) : 0.f;
            att[nn] = e; ssum += e;
        }
        float inv = (ssum > 0.f) ? 1.f / ssum : 0.f;
        for (int nn = 0; nn < 48; nn++) att[nn] *= inv;
        sany = any;
    }
    __syncthreads();
    for (int d = tid; d < Dm; d += 256) {
        float a = 0.f;
#pragma unroll 8
        for (int nn = 0; nn < 48; nn++) {
            float c = att[nn];
            if (c != 0.f) a += c * g_nodes[(l * 48 + nn) * Dm + d];
        }
        g_sym[l * Dm + d] = sany ? a : 0.f;
    }
}

// ---------------- fused: split-K reduce (fuse GEMM, +bias+relu) + head + log_softmax ----------------
__global__ __launch_bounds__(256)
void k_reduce_out(const float* __restrict__ part, const float* __restrict__ bfuse,
                  const float* __restrict__ Wout, const float* __restrict__ bout,
                  float* __restrict__ out)
{
    int l = blockIdx.x;
    int tid = threadIdx.x;  // 256
    int w = tid >> 5, lane = tid & 31;
    __shared__ float hs[Dm];
    __shared__ float logits[8];
    __shared__ float lse;
    for (int d = tid; d < Dm; d += 256) {
        float a = 0.f;
#pragma unroll
        for (int ks = 0; ks < 12; ks++) a += part[(size_t)ks * (Lq * Dm) + l * Dm + d];
        a += bfuse[d];
        hs[d] = fmaxf(a, 0.f);
    }
    __syncthreads();
    if (w < Cm) {
        float a = 0.f;
        for (int d = lane; d < Dm; d += 32) a += hs[d] * Wout[d * Cm + w];
        a = warp_sum(a);
        if (lane == 0) logits[w] = a + bout[w];
    }
    __syncthreads();
    if (tid == 0) {
        float m = logits[0];
        for (int c = 1; c < Cm; c++) m = fmaxf(m, logits[c]);
        float ssum = 0.f;
        for (int c = 0; c < Cm; c++) ssum += __expf(logits[c] - m);
        lse = m + logf(ssum);
    }
    __syncthreads();
    if (tid < Cm) out[l * Cm + tid] = logits[tid] - lse;
}

// ---------------- launch ----------------
extern "C" void kernel_launch(void* const* d_in, const int* in_sizes, int n_in,
                              void* d_out, int out_size)
{
    (void)in_sizes; (void)n_in; (void)out_size;
    const float* utt   = (const float*)d_in[0];
    const int*   esrc  = (const int*)d_in[1];
    const int*   edst  = (const int*)d_in[2];
    const int*   etyp  = (const int*)d_in[3];
    const int*   csrc  = (const int*)d_in[4];
    const int*   cdst  = (const int*)d_in[5];
    const float* cwgt  = (const float*)d_in[6];
    const float* csen  = (const float*)d_in[7];
    const float* table = (const float*)d_in[8];
    const float* Wb    = (const float*)d_in[9];
    const float* comp  = (const float*)d_in[10];
    const float* Wself = (const float*)d_in[11];
    const float* brg   = (const float*)d_in[12];
    const float* Wq    = (const float*)d_in[13];
    const float* Wk    = (const float*)d_in[14];
    const float* Wv    = (const float*)d_in[15];
    const float* Wo    = (const float*)d_in[16];
    const float* rvec  = (const float*)d_in[17];
    const float* Wfuse = (const float*)d_in[18];
    const float* bfuse = (const float*)d_in[19];
    const float* Wout  = (const float*)d_in[20];
    const float* bout  = (const float*)d_in[21];

    // host-side symbol lookups (no stream ops, capture-safe); cached across calls
    static float* pLin = nullptr; static float* pCtx = nullptr; static float* pRel = nullptr;
    static float* pPart = nullptr;
    if (!pLin) {
        cudaGetSymbolAddress((void**)&pLin,  g_Lin);
        cudaGetSymbolAddress((void**)&pCtx,  g_ctx);
        cudaGetSymbolAddress((void**)&pRel,  g_relatt);
        cudaGetSymbolAddress((void**)&pPart, g_part);
    }

    // 1) six fused linears, split-K=4 (kChunk 80): grid 29x4x4 = 464 blocks
    BPtrs six; six.p[0] = Wb; six.p[1] = Wb + 300 * 300; six.p[2] = Wself;
    six.p[3] = Wq; six.p[4] = Wk; six.p[5] = Wv;
    sgemm_splitk<0, 1><<<dim3(29, 4, 4), 256>>>(utt, six, pPart, Lq, 1800, Dm, 80);
    reduce_splitk<<<(Lq * 1800 / 4 + 255) / 256, 256>>>((const float4*)pPart, (float4*)pLin,
                                                        Lq * 1800 / 4, 4);

    // 2) merged RGCN + windowed attention (512 blocks; both read only g_Lin)
    k_rgcn_relatt<<<2 * Lq, 256>>>(brg, esrc, edst, etyp, comp);

    // 3) ctx @ Wo, split-K=7 (kChunk 48): grid 5x4x7 = 140 blocks
    BPtrs bo; bo.p[0] = Wo; bo.p[1] = bo.p[2] = bo.p[3] = bo.p[4] = bo.p[5] = nullptr;
    sgemm_splitk<0, 0><<<dim3(5, 4, 7), 256>>>(pCtx, bo, pPart, Lq, Dm, Dm, 48);
    reduce_splitk<<<(Lq * Dm / 4 + 255) / 256, 256>>>((const float4*)pPart, (float4*)pRel,
                                                      Lq * Dm / 4, 7);

    // 4) concept-graph nodes (single-wave gather)
    k_nodes<<<3 * Lq * Sm, 256>>>(table, csrc, cdst, cwgt, csen, rvec);

    // 5) node attention -> sym
    k_sym<<<Lq, 256>>>();

    // 6) fused [hidden|relatt|sym] @ Wfuse, split-K=12 (kChunk 80): grid 5x4x12 = 240 blocks
    BPtrs bf; bf.p[0] = Wfuse; bf.p[1] = bf.p[2] = bf.p[3] = bf.p[4] = bf.p[5] = nullptr;
    sgemm_splitk<1, 0><<<dim3(5, 4, 12), 256>>>(nullptr, bf, pPart, Lq, Dm, 900, 80);

    // 7) fused: reduce(+bias+relu) + head + log_softmax, one block per row
    k_reduce_out<<<Lq, 256>>>(pPart, bfuse, Wout, bout, (float*)d_out);
}

// round 14
// speedup vs baseline: 1.2259x; 1.1988x over previous
#include <cuda_runtime.h>
#include <math.h>

#define Lq 256
#define Dm 300
#define Sm 16
#define SK 16
#define Em 2048
#define Cm 7
#define NEGV -1000000000.0f

// ---------------- scratch (device globals; no allocation) ----------------
__device__ float g_Lin[Lq * 1800];       // [P0 | P1 | Hself | Q | K | V] per row
__device__ float g_hidden[Lq * Dm];
__device__ float g_ctx[Lq * Dm];
__device__ float g_relatt[Lq * Dm];
__device__ float g_nodes[Lq * 48 * Dm];  // 14.7 MB
__device__ float g_score[Lq * 48];
__device__ int   g_nmask[Lq * 48];
__device__ float g_sym[Lq * Dm];
__device__ float g_part[4 * Lq * 1800];  // split-K partials (max: Lin KS=4), 7.4 MB

struct BPtrs { const float* p[6]; };

__device__ __forceinline__ float warp_sum(float v) {
#pragma unroll
    for (int o = 16; o; o >>= 1) v += __shfl_xor_sync(0xffffffffu, v, o);
    return v;
}
__device__ __forceinline__ float warp_max(float v) {
#pragma unroll
    for (int o = 16; o; o >>= 1) v = fmaxf(v, __shfl_xor_sync(0xffffffffu, v, o));
    return v;
}

// ---------------- split-K tiled SGEMM, 2-stage double buffer ----------------
// AMODE 0: A is the passed pointer, row-major M x Kd
// AMODE 1: A row l is the concat [g_hidden[l] | g_relatt[l] | g_sym[l]] (Kd = 900)
// BMODE 0: B = B.p[0], row-major Kd x N (ldb = N)
// BMODE 1: six concatenated 300x300 matrices: N = 1800, col c -> matrix c/300
// Each thread owns ONE 16B A-chunk and ONE 16B B-chunk per k-tile; loads for
// tile t+1 are issued before computing tile t (latency hidden under 256 FMAs).
// Requires: Kd % 4 == 0, kChunk % 4 == 0 (chunk validity is uniform per 4-group).
template <int AMODE, int BMODE>
__global__ __launch_bounds__(256)
void sgemm_splitk(const float* __restrict__ A, BPtrs B, float* __restrict__ Cpart,
                  int M, int N, int Kd, int kChunk)
{
    const int BM = 64, BN = 64, BK = 16;
    __shared__ __align__(16) float As[2][BK][BM];
    __shared__ __align__(16) float Bs[2][BK][BN];
    int tid = threadIdx.x;                 // 256 threads
    int tx = tid & 15, ty = tid >> 4;
    int rowBase = blockIdx.y * BM;
    int colBase = blockIdx.x * BN;
    int ks = blockIdx.z;
    int kBeg = ks * kChunk;
    int kEnd = min(Kd, kBeg + kChunk);
    int nT = (kEnd - kBeg + BK - 1) / BK;

    // chunk ownership
    int aR = tid >> 2, aK = (tid & 3) * 4;   // A: row aR (0..63), k-offset aK (0,4,8,12)
    int bK = tid >> 4, bC = (tid & 15) * 4;  // B: k-row bK (0..15), col-offset bC

    float acc[4][4];
#pragma unroll
    for (int i = 0; i < 4; i++)
#pragma unroll
        for (int j = 0; j < 4; j++) acc[i][j] = 0.f;

    float4 ra4, rb4;
    auto loadA = [&](int k0, float4& r) {
        int gr = rowBase + aR, gk = k0 + aK;
        r.x = r.y = r.z = r.w = 0.f;
        if (gr < M && gk < kEnd) {
            if (AMODE == 1) {
                const float* src;
                if (gk < 300)      src = g_hidden + gr * 300 + gk;
                else if (gk < 600) src = g_relatt + gr * 300 + (gk - 300);
                else               src = g_sym    + gr * 300 + (gk - 600);
                r = *(const float4*)src;
            } else {
                r = *(const float4*)(A + (size_t)gr * Kd + gk);
            }
        }
    };
    auto loadB = [&](int k0, float4& r) {
        int gk = k0 + bK, gc = colBase + bC;
        r.x = r.y = r.z = r.w = 0.f;
        if (gk < kEnd && gc < N) {
            if (BMODE == 1) {
                int m = gc / 300, o = gc - m * 300;
                r = *(const float4*)(B.p[m] + (size_t)gk * 300 + o);
            } else {
                r = *(const float4*)(B.p[0] + (size_t)gk * N + gc);
            }
        }
    };

    // prologue: stage 0
    loadA(kBeg, ra4); loadB(kBeg, rb4);
    As[0][aK + 0][aR] = ra4.x; As[0][aK + 1][aR] = ra4.y;
    As[0][aK + 2][aR] = ra4.z; As[0][aK + 3][aR] = ra4.w;
    *(float4*)&Bs[0][bK][bC] = rb4;
    __syncthreads();

    for (int t = 0; t < nT; t++) {
        int cur = t & 1, nxt = cur ^ 1;
        bool more = (t + 1 < nT);
        if (more) {                       // issue next-tile loads BEFORE compute
            loadA(kBeg + (t + 1) * BK, ra4);
            loadB(kBeg + (t + 1) * BK, rb4);
        }
#pragma unroll
        for (int kk = 0; kk < BK; kk++) {
            float ra[4], rb[4];
#pragma unroll
            for (int i = 0; i < 4; i++) ra[i] = As[cur][kk][ty * 4 + i];
#pragma unroll
            for (int j = 0; j < 4; j++) rb[j] = Bs[cur][kk][tx * 4 + j];
#pragma unroll
            for (int i = 0; i < 4; i++)
#pragma unroll
                for (int j = 0; j < 4; j++) acc[i][j] += ra[i] * rb[j];
        }
        if (more) {
            As[nxt][aK + 0][aR] = ra4.x; As[nxt][aK + 1][aR] = ra4.y;
            As[nxt][aK + 2][aR] = ra4.z; As[nxt][aK + 3][aR] = ra4.w;
            *(float4*)&Bs[nxt][bK][bC] = rb4;
        }
        __syncthreads();
    }

    float* Cp = Cpart + (size_t)ks * M * N;
#pragma unroll
    for (int i = 0; i < 4; i++) {
        int gr = rowBase + ty * 4 + i;
        if (gr >= M) continue;
#pragma unroll
        for (int j = 0; j < 4; j++) {
            int gc = colBase + tx * 4 + j;
            if (gc >= N) continue;
            Cp[gr * N + gc] = acc[i][j];
        }
    }
}

// ---------------- split-K reduction: out[i] = sum_ks part[ks][i] ----------------
__global__ __launch_bounds__(256)
void reduce_splitk(const float4* __restrict__ part, float4* __restrict__ out,
                   int n4, int KS)
{
    int i = blockIdx.x * blockDim.x + threadIdx.x;
    if (i >= n4) return;
    float4 a = part[i];
    for (int ks = 1; ks < KS; ks++) {
        float4 b = part[(size_t)ks * n4 + i];
        a.x += b.x; a.y += b.y; a.z += b.z; a.w += b.w;
    }
    out[i] = a;
}

// ---------------- merged RGCN + windowed attention (both read only g_Lin) ----------------
__global__ __launch_bounds__(256)
void k_rgcn_relatt(const float* __restrict__ b_rgcn,
                   const int* __restrict__ esrc, const int* __restrict__ edst,
                   const int* __restrict__ etyp, const float* __restrict__ comp)
{
    int tid = threadIdx.x;  // 256
    if (blockIdx.x < Lq) {
        // ---- RGCN ----
        int l = blockIdx.x;
        __shared__ int sdst[Em];
        for (int i = tid; i < Em; i += 256) sdst[i] = edst[i];
        int d0 = tid, d1 = tid + 256;
        bool h1 = (d1 < Dm);
        float acc0 = g_Lin[l * 1800 + 600 + d0] + b_rgcn[d0];
        float acc1 = h1 ? g_Lin[l * 1800 + 600 + d1] + b_rgcn[d1] : 0.f;
        __syncthreads();
        for (int e = 0; e < Em; e++) {
            if (sdst[e] == l) {
                int s = esrc[e]; int t = etyp[e];
                float c0 = comp[2 * t], c1 = comp[2 * t + 1];
                const float* p0 = g_Lin + s * 1800;
                const float* p1 = p0 + 300;
                acc0 += c0 * p0[d0] + c1 * p1[d0];
                if (h1) acc1 += c0 * p0[d1] + c1 * p1[d1];
            }
        }
        g_hidden[l * Dm + d0] = acc0;
        if (h1) g_hidden[l * Dm + d1] = acc1;
    } else {
        // ---- windowed attention (middle query only) -> ctx ----
        int l = blockIdx.x - Lq;
        int w = tid >> 5, lane = tid & 31;
        __shared__ float ssc[2][3];
        __shared__ float sat[2][3];
        int w0 = max(l - 1, 0), w1 = l, w2 = min(l + 1, Lq - 1);
        int wins[3] = {w0, w1, w2};
        if (w < 6) {
            int h = w / 3, j = w - h * 3;
            const float* q  = g_Lin + l * 1800 + 900 + h * 150;
            const float* kk = g_Lin + wins[j] * 1800 + 1200 + h * 150;
            float a = 0.f;
            for (int d = lane; d < 150; d += 32) a += q[d] * kk[d];
            a = warp_sum(a);
            if (lane == 0) ssc[h][j] = a * (1.0f / sqrtf(150.0f));
        }
        __syncthreads();
        if (tid < 2) {
            int h = tid;
            float m = fmaxf(ssc[h][0], fmaxf(ssc[h][1], ssc[h][2]));
            float e0 = __expf(ssc[h][0] - m), e1 = __expf(ssc[h][1] - m), e2 = __expf(ssc[h][2] - m);
            float inv = 1.0f / (e0 + e1 + e2);
            sat[h][0] = e0 * inv; sat[h][1] = e1 * inv; sat[h][2] = e2 * inv;
        }
        __syncthreads();
        for (int d = tid; d < Dm; d += 256) {
            int h = d / 150;
            float v = sat[h][0] * g_Lin[w0 * 1800 + 1500 + d]
                    + sat[h][1] * g_Lin[w1 * 1800 + 1500 + d]
                    + sat[h][2] * g_Lin[w2 * 1800 + 1500 + d];
            g_ctx[l * Dm + d] = v;
        }
    }
}

// ---------------- concept-graph node builder: one block per (b,l,s), 256 threads ----------------
// gather issued as 6 batched LDG.128 per thread (MLP=6) in a single wave
__global__ __launch_bounds__(256)
void k_nodes(const float* __restrict__ table,
             const int* __restrict__ src_ids, const int* __restrict__ dst_ids,
             const float* __restrict__ wgt, const float* __restrict__ sentic,
             const float* __restrict__ rvecs)
{
    int idx = blockIdx.x;
    int s = idx & 15;
    int l = (idx >> 4) & 255;
    int b = idx >> 12;
    int n = b * Sm + s;
    int tid = threadIdx.x;            // 256
    int w = tid >> 5, lane = tid & 31;

    __shared__ __align__(16) float sm_rel[Dm], sm_src[Dm], sm_rv[Dm], sm_sr[Dm];
    __shared__ __align__(16) float sm_dst[SK][Dm];
    __shared__ float sm_d1[SK], sm_nr[SK], sm_d2[SK], sm_coef[SK];
    __shared__ int sm_id[SK];
    __shared__ float sm_red[8];
    __shared__ float sm_rn;

    int sid = src_ids[(b * Lq + l) * Sm + s];
    int nrow = (l * 48 + n) * Dm;
    if (sid < 0) {
        // no zero-fill of g_nodes needed: k_sym weights these rows with att==0 exactly
        if (tid == 0) { g_score[l * 48 + n] = NEGV; g_nmask[l * 48 + n] = 0; }
        return;
    }
    if (tid < SK) sm_id[tid] = dst_ids[((b * Lq + l) * Sm + s) * SK + tid];
    __syncthreads();

    // ---- single gather wave, batched: 1200 dst f4 + 75 rel + 75 src + 75 rv = 1425
    {
        const float4* relr = (const float4*)(g_relatt + l * Dm);
        const float4* srcr = (const float4*)(table + (long)sid * Dm);
        const float4* rvr  = (const float4*)(rvecs + b * Dm);
        const float4* srcp[6];
#pragma unroll
        for (int j = 0; j < 6; j++) {
            int i = tid + j * 256;
            srcp[j] = nullptr;
            if (i < 1425) {
                if (i < 1200) {
                    int k = i / 75, d4 = i - k * 75;
                    int id = sm_id[k];
                    srcp[j] = (id >= 0) ? ((const float4*)(table + (long)id * Dm) + d4) : nullptr;
                } else if (i < 1275) srcp[j] = relr + (i - 1200);
                else if (i < 1350)   srcp[j] = srcr + (i - 1275);
                else                 srcp[j] = rvr  + (i - 1350);
            }
        }
        float4 v[6];
#pragma unroll
        for (int j = 0; j < 6; j++) {
            if (srcp[j]) v[j] = *srcp[j];
            else         { v[j].x = v[j].y = v[j].z = v[j].w = 0.f; }
        }
#pragma unroll
        for (int j = 0; j < 6; j++) {
            int i = tid + j * 256;
            if (i < 1425) {
                if (i < 1200) {
                    int k = i / 75, d4 = i - k * 75;
                    ((float4*)&sm_dst[k][0])[d4] = v[j];
                } else if (i < 1275) ((float4*)sm_rel)[i - 1200] = v[j];
                else if (i < 1350)   ((float4*)sm_src)[i - 1275] = v[j];
                else                 ((float4*)sm_rv)[i - 1350]  = v[j];
            }
        }
    }
    __syncthreads();

    // pn = |rel|^2 ; sm_sr = src * rv
    float pn = 0.f;
    for (int d = tid; d < Dm; d += 256) {
        float r = sm_rel[d];
        pn += r * r;
        sm_sr[d] = sm_src[d] * sm_rv[d];
    }
    pn = warp_sum(pn);
    if (lane == 0) sm_red[w] = pn;
    __syncthreads();
    if (tid == 0) {
        float t = 0.f;
#pragma unroll
        for (int i = 0; i < 8; i++) t += sm_red[i];
        sm_rn = sqrtf(t);
    }
    __syncthreads();

    // 8 warps x 2 k's each: three dots per k
    for (int k = w; k < SK; k += 8) {
        float a1 = 0.f, a2 = 0.f, a3 = 0.f;
        for (int d = lane; d < Dm; d += 32) {
            float x = sm_dst[k][d];
            a1 += sm_rel[d] * x;
            a2 += x * x;
            a3 += sm_sr[d] * x;
        }
        a1 = warp_sum(a1); a2 = warp_sum(a2); a3 = warp_sum(a3);
        if (lane == 0) { sm_d1[k] = a1; sm_nr[k] = a2; sm_d2[k] = a3; }
    }
    __syncthreads();

    if (tid < 32) {
        int k = lane;
        bool valid = (k < SK) && (sm_id[k] >= 0);
        float omega = -INFINITY;
        if (valid) {
            long base = ((long)(b * Lq + l) * Sm + s) * SK + k;
            float cosv = fabsf(sm_d1[k]) / (sm_rn * sqrtf(sm_nr[k]) + 1e-8f);
            omega = 0.5f * wgt[base] * cosv + 0.5f * fabsf(sentic[base]);
        }
        float m = warp_max(omega);
        float e = valid ? __expf(omega - m) : 0.f;
        float ssum = warp_sum(e);
        float alpha1 = (ssum > 0.f) ? e / ssum : 0.f;
        float sv = valid ? alpha1 * sm_d2[k] : -INFINITY;
        float m2 = warp_max(sv);
        float e2 = valid ? __expf(sv - m2) : 0.f;
        float ssum2 = warp_sum(e2);
        float alpha2 = (ssum2 > 0.f) ? e2 / ssum2 : 0.f;
        if (k < SK) sm_coef[k] = alpha1 * alpha2;
    }
    __syncthreads();

    float psc = 0.f;
    for (int d = tid; d < Dm; d += 256) {
        float a = 0.f;
#pragma unroll
        for (int k = 0; k < SK; k++) a += sm_coef[k] * sm_dst[k][d];
        float nd = sm_src[d] + sm_rv[d] * a;
        g_nodes[nrow + d] = nd;
        psc += nd * sm_rel[d];
    }
    psc = warp_sum(psc);
    if (lane == 0) sm_red[w] = psc;
    __syncthreads();
    if (tid == 0) {
        float t = 0.f;
#pragma unroll
        for (int i = 0; i < 8; i++) t += sm_red[i];
        g_score[l * 48 + n] = t;
        g_nmask[l * 48 + n] = 1;
    }
}

// ---------------- node-level attention -> sym (float4) ----------------
__global__ __launch_bounds__(256)
void k_sym()
{
    int l = blockIdx.x;
    int tid = threadIdx.x;  // 256
    __shared__ float att[48];
    __shared__ int sany;
    if (tid == 0) {
        float m = -INFINITY; int any = 0;
        for (int nn = 0; nn < 48; nn++)
            if (g_nmask[l * 48 + nn]) { any = 1; m = fmaxf(m, g_score[l * 48 + nn]); }
        float ssum = 0.f;
        for (int nn = 0; nn < 48; nn++) {
            float e = g_nmask[l * 48 + nn] ? __expf(g_score[l * 48 + nn] - m) : 0.f;
            att[nn] = e; ssum += e;
        }
        float inv = (ssum > 0.f) ? 1.f / ssum : 0.f;
        for (int nn = 0; nn < 48; nn++) att[nn] *= inv;
        sany = any;
    }
    __syncthreads();
    // 75 float4 chunks per row
    for (int d4 = tid; d4 < 75; d4 += 256) {
        float4 a; a.x = a.y = a.z = a.w = 0.f;
        for (int nn = 0; nn < 48; nn++) {
            float c = att[nn];
            if (c != 0.f) {
                float4 v = *((const float4*)(g_nodes + (l * 48 + nn) * Dm) + d4);
                a.x += c * v.x; a.y += c * v.y; a.z += c * v.z; a.w += c * v.w;
            }
        }
        if (!sany) { a.x = a.y = a.z = a.w = 0.f; }
        *((float4*)(g_sym + l * Dm) + d4) = a;
    }
}

// ---------------- fused: split-K reduce (fuse GEMM, +bias+relu) + head + log_softmax ----------------
__global__ __launch_bounds__(256)
void k_reduce_out(const float* __restrict__ part, const float* __restrict__ bfuse,
                  const float* __restrict__ Wout, const float* __restrict__ bout,
                  float* __restrict__ out)
{
    int l = blockIdx.x;
    int tid = threadIdx.x;  // 256
    int w = tid >> 5, lane = tid & 31;
    __shared__ __align__(16) float hs[Dm];
    __shared__ float logits[8];
    __shared__ float lse;
    for (int d4 = tid; d4 < 75; d4 += 256) {
        float4 a; a.x = a.y = a.z = a.w = 0.f;
#pragma unroll
        for (int ks = 0; ks < 12; ks++) {
            float4 v = *((const float4*)(part + (size_t)ks * (Lq * Dm) + l * Dm) + d4);
            a.x += v.x; a.y += v.y; a.z += v.z; a.w += v.w;
        }
        float4 bv = *((const float4*)bfuse + d4);
        a.x = fmaxf(a.x + bv.x, 0.f); a.y = fmaxf(a.y + bv.y, 0.f);
        a.z = fmaxf(a.z + bv.z, 0.f); a.w = fmaxf(a.w + bv.w, 0.f);
        *((float4*)hs + d4) = a;
    }
    __syncthreads();
    if (w < Cm) {
        float a = 0.f;
        for (int d = lane; d < Dm; d += 32) a += hs[d] * Wout[d * Cm + w];
        a = warp_sum(a);
        if (lane == 0) logits[w] = a + bout[w];
    }
    __syncthreads();
    if (tid == 0) {
        float m = logits[0];
        for (int c = 1; c < Cm; c++) m = fmaxf(m, logits[c]);
        float ssum = 0.f;
        for (int c = 0; c < Cm; c++) ssum += __expf(logits[c] - m);
        lse = m + logf(ssum);
    }
    __syncthreads();
    if (tid < Cm) out[l * Cm + tid] = logits[tid] - lse;
}

// ---------------- launch ----------------
extern "C" void kernel_launch(void* const* d_in, const int* in_sizes, int n_in,
                              void* d_out, int out_size)
{
    (void)in_sizes; (void)n_in; (void)out_size;
    const float* utt   = (const float*)d_in[0];
    const int*   esrc  = (const int*)d_in[1];
    const int*   edst  = (const int*)d_in[2];
    const int*   etyp  = (const int*)d_in[3];
    const int*   csrc  = (const int*)d_in[4];
    const int*   cdst  = (const int*)d_in[5];
    const float* cwgt  = (const float*)d_in[6];
    const float* csen  = (const float*)d_in[7];
    const float* table = (const float*)d_in[8];
    const float* Wb    = (const float*)d_in[9];
    const float* comp  = (const float*)d_in[10];
    const float* Wself = (const float*)d_in[11];
    const float* brg   = (const float*)d_in[12];
    const float* Wq    = (const float*)d_in[13];
    const float* Wk    = (const float*)d_in[14];
    const float* Wv    = (const float*)d_in[15];
    const float* Wo    = (const float*)d_in[16];
    const float* rvec  = (const float*)d_in[17];
    const float* Wfuse = (const float*)d_in[18];
    const float* bfuse = (const float*)d_in[19];
    const float* Wout  = (const float*)d_in[20];
    const float* bout  = (const float*)d_in[21];

    // host-side symbol lookups (no stream ops, capture-safe); cached across calls
    static float* pLin = nullptr; static float* pCtx = nullptr; static float* pRel = nullptr;
    static float* pPart = nullptr;
    if (!pLin) {
        cudaGetSymbolAddress((void**)&pLin,  g_Lin);
        cudaGetSymbolAddress((void**)&pCtx,  g_ctx);
        cudaGetSymbolAddress((void**)&pRel,  g_relatt);
        cudaGetSymbolAddress((void**)&pPart, g_part);
    }

    // 1) six fused linears, split-K=4 (kChunk 80): grid 29x4x4 = 464 blocks
    BPtrs six; six.p[0] = Wb; six.p[1] = Wb + 300 * 300; six.p[2] = Wself;
    six.p[3] = Wq; six.p[4] = Wk; six.p[5] = Wv;
    sgemm_splitk<0, 1><<<dim3(29, 4, 4), 256>>>(utt, six, pPart, Lq, 1800, Dm, 80);
    reduce_splitk<<<(Lq * 1800 / 4 + 255) / 256, 256>>>((const float4*)pPart, (float4*)pLin,
                                                        Lq * 1800 / 4, 4);

    // 2) merged RGCN + windowed attention (512 blocks; both read only g_Lin)
    k_rgcn_relatt<<<2 * Lq, 256>>>(brg, esrc, edst, etyp, comp);

    // 3) ctx @ Wo, split-K=7 (kChunk 48): grid 5x4x7 = 140 blocks
    BPtrs bo; bo.p[0] = Wo; bo.p[1] = bo.p[2] = bo.p[3] = bo.p[4] = bo.p[5] = nullptr;
    sgemm_splitk<0, 0><<<dim3(5, 4, 7), 256>>>(pCtx, bo, pPart, Lq, Dm, Dm, 48);
    reduce_splitk<<<(Lq * Dm / 4 + 255) / 256, 256>>>((const float4*)pPart, (float4*)pRel,
                                                      Lq * Dm / 4, 7);

    // 4) concept-graph nodes (batched single-wave gather)
    k_nodes<<<3 * Lq * Sm, 256>>>(table, csrc, cdst, cwgt, csen, rvec);

    // 5) node attention -> sym
    k_sym<<<Lq, 256>>>();

    // 6) fused [hidden|relatt|sym] @ Wfuse, split-K=12 (kChunk 80): grid 5x4x12 = 240 blocks
    BPtrs bf; bf.p[0] = Wfuse; bf.p[1] = bf.p[2] = bf.p[3] = bf.p[4] = bf.p[5] = nullptr;
    sgemm_splitk<1, 0><<<dim3(5, 4, 12), 256>>>(nullptr, bf, pPart, Lq, Dm, 900, 80);

    // 7) fused: reduce(+bias+relu) + head + log_softmax, one block per row
    k_reduce_out<<<Lq, 256>>>(pPart, bfuse, Wout, bout, (float*)d_out);
}